// round 2
// baseline (speedup 1.0000x reference)
#include <cuda_runtime.h>

// Problem constants (fixed by the dataset)
#define BSZ   16384
#define KNUM  1000
#define DIMN  768

#define WARPS_PER_BLOCK 8
#define THREADS (WARPS_PER_BLOCK * 32)

// DIMN/4 float4 per row = 192; per lane = 192/32 = 6
#define V4_PER_LANE 6
// mask row: KNUM/4 = 250 float4
#define MASK_V4 (KNUM / 4)

__global__ __launch_bounds__(THREADS)
void css_kernel(const float* __restrict__ mask,   // [BS, K]
                const float* __restrict__ z,      // [BS, DIM]
                const float* __restrict__ S,      // [K, 2*DIM]
                const float* __restrict__ A,      // [K, 2]
                const float* __restrict__ LG,     // [K, 2]
                float* __restrict__ out)          // [BS, DIM]
{
    const int warp = (blockIdx.x * THREADS + threadIdx.x) >> 5;
    const int lane = threadIdx.x & 31;
    if (warp >= BSZ) return;

    // ---- 1. Find the one-hot index for this sample (coalesced float4 scan)
    const float4* __restrict__ mrow =
        reinterpret_cast<const float4*>(mask + (size_t)warp * KNUM);
    int idx = 0;
    #pragma unroll
    for (int it = 0; it < 8; it++) {
        int i = lane + 32 * it;
        if (i < MASK_V4) {
            float4 v = __ldg(&mrow[i]);
            if (v.x != 0.0f) idx = 4 * i + 0;
            if (v.y != 0.0f) idx = 4 * i + 1;
            if (v.z != 0.0f) idx = 4 * i + 2;
            if (v.w != 0.0f) idx = 4 * i + 3;
        }
    }
    #pragma unroll
    for (int o = 16; o > 0; o >>= 1)
        idx = max(idx, __shfl_xor_sync(0xffffffffu, idx, o));

    // ---- 2. Per-dipole scalars (tiny gathers; L2/L1 resident)
    const float a0 = __ldg(&A[2 * idx + 0]);
    const float a1 = __ldg(&A[2 * idx + 1]);
    const float g0 = __expf(__ldg(&LG[2 * idx + 0]));
    const float g1 = __expf(__ldg(&LG[2 * idx + 1]));

    const float4* __restrict__ zrow =
        reinterpret_cast<const float4*>(z + (size_t)warp * DIMN);
    const float4* __restrict__ s0r =
        reinterpret_cast<const float4*>(S + (size_t)idx * (2 * DIMN));
    const float4* __restrict__ s1r = s0r + (DIMN / 4);

    // ---- 3. Pass 1: six dot products, nothing retained in registers
    float zz = 0.0f, ss0 = 0.0f, ss1 = 0.0f;
    float c0 = 0.0f, c1 = 0.0f, s01 = 0.0f;
    #pragma unroll 2
    for (int i = 0; i < V4_PER_LANE; i++) {
        const int p = lane + 32 * i;
        float4 zv = __ldg(&zrow[p]);
        float4 s0 = __ldg(&s0r[p]);
        float4 s1 = __ldg(&s1r[p]);
        zz  = fmaf(zv.x, zv.x, zz);   zz  = fmaf(zv.y, zv.y, zz);
        zz  = fmaf(zv.z, zv.z, zz);   zz  = fmaf(zv.w, zv.w, zz);
        ss0 = fmaf(s0.x, s0.x, ss0);  ss0 = fmaf(s0.y, s0.y, ss0);
        ss0 = fmaf(s0.z, s0.z, ss0);  ss0 = fmaf(s0.w, s0.w, ss0);
        ss1 = fmaf(s1.x, s1.x, ss1);  ss1 = fmaf(s1.y, s1.y, ss1);
        ss1 = fmaf(s1.z, s1.z, ss1);  ss1 = fmaf(s1.w, s1.w, ss1);
        c0  = fmaf(zv.x, s0.x, c0);   c0  = fmaf(zv.y, s0.y, c0);
        c0  = fmaf(zv.z, s0.z, c0);   c0  = fmaf(zv.w, s0.w, c0);
        c1  = fmaf(zv.x, s1.x, c1);   c1  = fmaf(zv.y, s1.y, c1);
        c1  = fmaf(zv.z, s1.z, c1);   c1  = fmaf(zv.w, s1.w, c1);
        s01 = fmaf(s0.x, s1.x, s01);  s01 = fmaf(s0.y, s1.y, s01);
        s01 = fmaf(s0.z, s1.z, s01);  s01 = fmaf(s0.w, s1.w, s01);
    }
    #pragma unroll
    for (int o = 16; o > 0; o >>= 1) {
        zz  += __shfl_xor_sync(0xffffffffu, zz,  o);
        ss0 += __shfl_xor_sync(0xffffffffu, ss0, o);
        ss1 += __shfl_xor_sync(0xffffffffu, ss1, o);
        c0  += __shfl_xor_sync(0xffffffffu, c0,  o);
        c1  += __shfl_xor_sync(0xffffffffu, c1,  o);
        s01 += __shfl_xor_sync(0xffffffffu, s01, o);
    }

    // ---- 4. All scalar algebra
    // sq_j = ||z - s_j||^2 = zz - 2 c_j + ss_j
    const float sq0 = zz - 2.0f * c0 + ss0;
    const float sq1 = zz - 2.0f * c1 + ss1;
    const float w0  = -2.0f * a0 * g0 * __expf(-g0 * sq0);
    const float w1  = -2.0f * a1 * g1 * __expf(-g1 * sq1);
    const float W   = w0 + w1;
    // zg = z . grad ; grad = W z - w0 s0 - w1 s1
    const float zg  = W * zz - w0 * c0 - w1 * c1;
    // proj = beta z - w0 s0 - w1 s1 ; beta = W - zg
    const float beta = W - zg;
    // ||proj||^2, fully scalar:
    const float nrm2 = beta * beta * zz
                     + w0 * w0 * ss0
                     + w1 * w1 * ss1
                     - 2.0f * beta * w0 * c0
                     - 2.0f * beta * w1 * c1
                     + 2.0f * w0 * w1 * s01;
    const float inv = rsqrtf(nrm2);

    const float bz  = beta * inv;   // coefficient of z
    const float b0  = -w0 * inv;    // coefficient of s0
    const float b1  = -w1 * inv;    // coefficient of s1

    // ---- 5. Pass 2: reload (L1/L2 hits) and write the normalized projection
    float4* __restrict__ orow =
        reinterpret_cast<float4*>(out + (size_t)warp * DIMN);
    #pragma unroll 2
    for (int i = 0; i < V4_PER_LANE; i++) {
        const int p = lane + 32 * i;
        float4 zv = __ldg(&zrow[p]);
        float4 s0 = __ldg(&s0r[p]);
        float4 s1 = __ldg(&s1r[p]);
        float4 o4;
        o4.x = fmaf(bz, zv.x, fmaf(b0, s0.x, b1 * s1.x));
        o4.y = fmaf(bz, zv.y, fmaf(b0, s0.y, b1 * s1.y));
        o4.z = fmaf(bz, zv.z, fmaf(b0, s0.z, b1 * s1.z));
        o4.w = fmaf(bz, zv.w, fmaf(b0, s0.w, b1 * s1.w));
        orow[p] = o4;
    }
}

extern "C" void kernel_launch(void* const* d_in, const int* in_sizes, int n_in,
                              void* d_out, int out_size)
{
    const float* mask = (const float*)d_in[0];   // [BS, K]
    const float* z    = (const float*)d_in[1];   // [BS, DIM]
    const float* S    = (const float*)d_in[2];   // [K, 2*DIM]
    const float* A    = (const float*)d_in[3];   // [K, 2]
    const float* LG   = (const float*)d_in[4];   // [K, 2]
    float* out        = (float*)d_out;           // [BS, DIM]

    const int blocks = BSZ / WARPS_PER_BLOCK;    // 2048
    css_kernel<<<blocks, THREADS>>>(mask, z, S, A, LG, out);
}

// round 3
// speedup vs baseline: 1.1772x; 1.1772x over previous
#include <cuda_runtime.h>

// Problem constants (fixed by the dataset)
#define BSZ   16384
#define KNUM  1000
#define DIMN  768

#define WARPS_PER_BLOCK 8
#define THREADS (WARPS_PER_BLOCK * 32)

// DIMN/4 float4 per row = 192; per lane = 192/32 = 6
#define V4_PER_LANE 6
// mask row: KNUM/4 = 250 float4
#define MASK_V4 (KNUM / 4)

__device__ __forceinline__ float4 ldcs4(const float4* p) {
    float4 v;
    asm volatile("ld.global.cs.v4.f32 {%0,%1,%2,%3}, [%4];"
                 : "=f"(v.x), "=f"(v.y), "=f"(v.z), "=f"(v.w) : "l"(p));
    return v;
}

__global__ __launch_bounds__(THREADS)
void css_kernel(const float* __restrict__ mask,   // [BS, K]
                const float* __restrict__ z,      // [BS, DIM]
                const float* __restrict__ S,      // [K, 2*DIM]
                const float* __restrict__ A,      // [K, 2]
                const float* __restrict__ LG,     // [K, 2]
                float* __restrict__ out)          // [BS, DIM]
{
    const int warp = (blockIdx.x * THREADS + threadIdx.x) >> 5;
    const int lane = threadIdx.x & 31;
    if (warp >= BSZ) return;

    // ---- 1. z loads first: independent of idx, latency hides under mask scan.
    //         Streamed (.cs): touched exactly once, retained in registers.
    const float4* __restrict__ zrow =
        reinterpret_cast<const float4*>(z + (size_t)warp * DIMN);
    float4 zr[V4_PER_LANE];
    #pragma unroll
    for (int i = 0; i < V4_PER_LANE; i++)
        zr[i] = ldcs4(&zrow[lane + 32 * i]);

    // ---- 2. One-hot index scan (streamed; touched once)
    const float4* __restrict__ mrow =
        reinterpret_cast<const float4*>(mask + (size_t)warp * KNUM);
    int idx = 0;
    #pragma unroll
    for (int it = 0; it < 8; it++) {
        int i = lane + 32 * it;
        if (i < MASK_V4) {
            float4 v = ldcs4(&mrow[i]);
            if (v.x != 0.0f) idx = 4 * i + 0;
            if (v.y != 0.0f) idx = 4 * i + 1;
            if (v.z != 0.0f) idx = 4 * i + 2;
            if (v.w != 0.0f) idx = 4 * i + 3;
        }
    }
    #pragma unroll
    for (int o = 16; o > 0; o >>= 1)
        idx = max(idx, __shfl_xor_sync(0xffffffffu, idx, o));

    // zz from retained z (overlaps idx reduction / gather latency)
    float zz = 0.0f;
    #pragma unroll
    for (int i = 0; i < V4_PER_LANE; i++) {
        zz = fmaf(zr[i].x, zr[i].x, zz);
        zz = fmaf(zr[i].y, zr[i].y, zz);
        zz = fmaf(zr[i].z, zr[i].z, zz);
        zz = fmaf(zr[i].w, zr[i].w, zz);
    }

    // ---- 3. Per-dipole scalars (tiny; L2-resident)
    const float a0 = __ldg(&A[2 * idx + 0]);
    const float a1 = __ldg(&A[2 * idx + 1]);
    const float g0 = __expf(__ldg(&LG[2 * idx + 0]));
    const float g1 = __expf(__ldg(&LG[2 * idx + 1]));

    const float4* __restrict__ s0r =
        reinterpret_cast<const float4*>(S + (size_t)idx * (2 * DIMN));
    const float4* __restrict__ s1r = s0r + (DIMN / 4);

    // ---- 4. Pass over S rows: 5 remaining dot products (S cached in L1
    //         via default policy; re-read in pass 2)
    float ss0 = 0.0f, ss1 = 0.0f, c0 = 0.0f, c1 = 0.0f, s01 = 0.0f;
    #pragma unroll
    for (int i = 0; i < V4_PER_LANE; i++) {
        const int p = lane + 32 * i;
        float4 s0 = __ldg(&s0r[p]);
        float4 s1 = __ldg(&s1r[p]);
        ss0 = fmaf(s0.x, s0.x, ss0);    ss0 = fmaf(s0.y, s0.y, ss0);
        ss0 = fmaf(s0.z, s0.z, ss0);    ss0 = fmaf(s0.w, s0.w, ss0);
        ss1 = fmaf(s1.x, s1.x, ss1);    ss1 = fmaf(s1.y, s1.y, ss1);
        ss1 = fmaf(s1.z, s1.z, ss1);    ss1 = fmaf(s1.w, s1.w, ss1);
        c0  = fmaf(zr[i].x, s0.x, c0);  c0  = fmaf(zr[i].y, s0.y, c0);
        c0  = fmaf(zr[i].z, s0.z, c0);  c0  = fmaf(zr[i].w, s0.w, c0);
        c1  = fmaf(zr[i].x, s1.x, c1);  c1  = fmaf(zr[i].y, s1.y, c1);
        c1  = fmaf(zr[i].z, s1.z, c1);  c1  = fmaf(zr[i].w, s1.w, c1);
        s01 = fmaf(s0.x, s1.x, s01);    s01 = fmaf(s0.y, s1.y, s01);
        s01 = fmaf(s0.z, s1.z, s01);    s01 = fmaf(s0.w, s1.w, s01);
    }
    #pragma unroll
    for (int o = 16; o > 0; o >>= 1) {
        zz  += __shfl_xor_sync(0xffffffffu, zz,  o);
        ss0 += __shfl_xor_sync(0xffffffffu, ss0, o);
        ss1 += __shfl_xor_sync(0xffffffffu, ss1, o);
        c0  += __shfl_xor_sync(0xffffffffu, c0,  o);
        c1  += __shfl_xor_sync(0xffffffffu, c1,  o);
        s01 += __shfl_xor_sync(0xffffffffu, s01, o);
    }

    // ---- 5. Scalar algebra
    const float sq0 = zz - 2.0f * c0 + ss0;
    const float sq1 = zz - 2.0f * c1 + ss1;
    const float w0  = -2.0f * a0 * g0 * __expf(-g0 * sq0);
    const float w1  = -2.0f * a1 * g1 * __expf(-g1 * sq1);
    const float W   = w0 + w1;
    const float zg  = W * zz - w0 * c0 - w1 * c1;       // z . grad
    const float beta = W - zg;                          // proj = beta z - w0 s0 - w1 s1
    const float nrm2 = beta * beta * zz
                     + w0 * w0 * ss0
                     + w1 * w1 * ss1
                     - 2.0f * beta * w0 * c0
                     - 2.0f * beta * w1 * c1
                     + 2.0f * w0 * w1 * s01;
    const float inv = rsqrtf(nrm2);

    const float bz = beta * inv;
    const float b0 = -w0 * inv;
    const float b1 = -w1 * inv;

    // ---- 6. Pass 2: re-read S rows (L1/L2 hits), combine with retained z, store
    float4* __restrict__ orow =
        reinterpret_cast<float4*>(out + (size_t)warp * DIMN);
    #pragma unroll
    for (int i = 0; i < V4_PER_LANE; i++) {
        const int p = lane + 32 * i;
        float4 s0 = __ldg(&s0r[p]);
        float4 s1 = __ldg(&s1r[p]);
        float4 o4;
        o4.x = fmaf(bz, zr[i].x, fmaf(b0, s0.x, b1 * s1.x));
        o4.y = fmaf(bz, zr[i].y, fmaf(b0, s0.y, b1 * s1.y));
        o4.z = fmaf(bz, zr[i].z, fmaf(b0, s0.z, b1 * s1.z));
        o4.w = fmaf(bz, zr[i].w, fmaf(b0, s0.w, b1 * s1.w));
        orow[p] = o4;
    }
}

extern "C" void kernel_launch(void* const* d_in, const int* in_sizes, int n_in,
                              void* d_out, int out_size)
{
    const float* mask = (const float*)d_in[0];   // [BS, K]
    const float* z    = (const float*)d_in[1];   // [BS, DIM]
    const float* S    = (const float*)d_in[2];   // [K, 2*DIM]
    const float* A    = (const float*)d_in[3];   // [K, 2]
    const float* LG   = (const float*)d_in[4];   // [K, 2]
    float* out        = (float*)d_out;           // [BS, DIM]

    const int blocks = BSZ / WARPS_PER_BLOCK;    // 2048
    css_kernel<<<blocks, THREADS>>>(mask, z, S, A, LG, out);
}